// round 4
// baseline (speedup 1.0000x reference)
#include <cuda_runtime.h>
#include <cstdint>
#include <math.h>

// bayes_55018531062578
//
// out[b] = sigmoid( BEVb[b]-BEVa[b] + (sum_{s<kapa} B[b,k*,s] - A[b,k*,s]) / kapa[b] )
// k*(b,s) = argmax_k ( log_softmax(mean)_k + gumbel(b,s,k) )
// gumbel noise: JAX partitionable threefry counter mode:
//   bits[i] = o0 ^ o1,  (o0,o1) = threefry2x32(key=(0,42), x=(hi32(i), lo32(i))),
//   u = bitcast((bits>>9)|0x3f800000) - 1           (hi32(i)=0 here, N < 2^32)
// argmax_k (l_k - log(-log(u+eps)+eps))  ==  argmax_k  w_k / t_k,
//   w_k = softmax(mean)_k,  t_k = -log2(u_k+eps)   (monotone transforms)

#define EPSF 1e-20f
#define EPSD 1e-20

__device__ __forceinline__ uint32_t rotl32(uint32_t x, int r) {
    return __funnelshift_l(x, x, r);
}

// threefry2x32, key (0,42), input (0, ctr); returns o0 ^ o1
__device__ __forceinline__ uint32_t threefry_xor(uint32_t ctr) {
    const uint32_t ks0 = 0u;
    const uint32_t ks1 = 42u;
    const uint32_t ks2 = 0x1BD11BDAu ^ 42u;

    uint32_t x0 = ks0;          // 0 + ks0
    uint32_t x1 = ctr + ks1;

#define TF4(a,b,c,d) \
    x0 += x1; x1 = rotl32(x1,(a)); x1 ^= x0; \
    x0 += x1; x1 = rotl32(x1,(b)); x1 ^= x0; \
    x0 += x1; x1 = rotl32(x1,(c)); x1 ^= x0; \
    x0 += x1; x1 = rotl32(x1,(d)); x1 ^= x0;

    TF4(13,15,26,6)   x0 += ks1; x1 += ks2 + 1u;
    TF4(17,29,16,24)  x0 += ks2; x1 += ks0 + 2u;
    TF4(13,15,26,6)   x0 += ks0; x1 += ks1 + 3u;
    TF4(17,29,16,24)  x0 += ks1; x1 += ks2 + 4u;
    TF4(13,15,26,6)   x0 += ks2; x1 += ks0 + 5u;
#undef TF4
    return x0 ^ x1;
}

__device__ __forceinline__ float bits_to_uniform(uint32_t bits) {
    return __uint_as_float((bits >> 9) | 0x3f800000u) - 1.0f;
}

__global__ __launch_bounds__(256, 8)
void bayes_kernel(const float* __restrict__ A,
                  const float* __restrict__ Bm,
                  const float* __restrict__ BEVa,
                  const float* __restrict__ BEVb,
                  const int*   __restrict__ kapa,
                  const float* __restrict__ mean,
                  float* __restrict__ out,
                  int B, int S) {
    const int b = blockIdx.x;
    const int tid = threadIdx.x;

    __shared__ float red[8];

    // Every thread computes softmax(mean) redundantly (4 floats, L1-broadcast).
    // No barriers needed before the reduction.
    const float m0 = mean[0], m1 = mean[1], m2 = mean[2], m3 = mean[3];
    const float mx = fmaxf(fmaxf(m0, m1), fmaxf(m2, m3));
    const float e0 = expf(m0 - mx), e1 = expf(m1 - mx);
    const float e2 = expf(m2 - mx), e3 = expf(m3 - mx);
    const float inv = 1.0f / (e0 + e1 + e2 + e3);
    float w[4] = {e0 * inv, e1 * inv, e2 * inv, e3 * inv};

    const int kap = kapa[b];
    const float* Ab = A  + (size_t)b * 4 * S;
    const float* Bb = Bm + (size_t)b * 4 * S;

    float diff = 0.0f;   // sum of (B - A) at selected k

    for (int s = tid; s < kap; s += 256) {
        const uint32_t base = ((uint32_t)b * (uint32_t)S + (uint32_t)s) * 4u;

        float u[4], q[4];
#pragma unroll
        for (int k = 0; k < 4; k++) {
            uint32_t bits = threefry_xor(base + (uint32_t)k);
            u[k] = bits_to_uniform(bits);
            float t = -__log2f(u[k] + EPSF);          // > 0
            q[k] = __fdividef(w[k], t);
        }

        int   kb = 0;
        float best = q[0], second = -1.0f;
        if (q[1] > best) { second = best; best = q[1]; kb = 1; } else second = q[1];
        if (q[2] > best) { second = best; best = q[2]; kb = 2; } else if (q[2] > second) second = q[2];
        if (q[3] > best) { second = best; best = q[3]; kb = 3; } else if (q[3] > second) second = q[3];

        if (best - second < best * 1e-3f) {
            // rare accurate fallback: replicate reference formula in double
            double lw[4];
            {
                double dm0 = (double)m0, dm1 = (double)m1;
                double dm2 = (double)m2, dm3 = (double)m3;
                double dmx = fmax(fmax(dm0, dm1), fmax(dm2, dm3));
                double de0 = exp(dm0 - dmx), de1 = exp(dm1 - dmx);
                double de2 = exp(dm2 - dmx), de3 = exp(dm3 - dmx);
                double lse = dmx + log(de0 + de1 + de2 + de3);
                lw[0] = dm0 - lse; lw[1] = dm1 - lse;
                lw[2] = dm2 - lse; lw[3] = dm3 - lse;
            }
            double bs = -1e300; int kk = 0;
#pragma unroll
            for (int k = 0; k < 4; k++) {
                double ud = (double)u[k] + EPSD;
                double inner = -log(ud) + EPSD;
                double sc = lw[k] - log(inner);
                if (sc > bs) { bs = sc; kk = k; }
            }
            kb = kk;
        }

        const size_t off = (size_t)kb * S + s;
        diff += Bb[off] - Ab[off];
    }

    // ---- uniform block reduction ----
#pragma unroll
    for (int o = 16; o > 0; o >>= 1)
        diff += __shfl_down_sync(0xffffffffu, diff, o);

    const int warp = tid >> 5;
    const int lane = tid & 31;
    if (lane == 0) red[warp] = diff;
    __syncthreads();

    if (tid == 0) {
        float tot = 0.0f;
#pragma unroll
        for (int wi = 0; wi < 8; wi++) tot += red[wi];
        float x = BEVb[b] - BEVa[b] + tot / (float)kap;
        out[b] = 1.0f / (1.0f + expf(-x));
    }
}

extern "C" void kernel_launch(void* const* d_in, const int* in_sizes, int n_in,
                              void* d_out, int out_size) {
    // metadata order: outcomeA, outcomeB, BEVa, BEVb, kapa, batch_size, features, mean
    const float* A    = (const float*)d_in[0];
    const float* Bm   = (const float*)d_in[1];
    const float* BEVa = (const float*)d_in[2];
    const float* BEVb = (const float*)d_in[3];
    const int*   kapa = (const int*)  d_in[4];

    // mean is the (only) 4-element input; locate it robustly from the tail
    const float* mean = (const float*)d_in[n_in - 1];
    for (int i = n_in - 1; i >= 5; --i) {
        if (in_sizes[i] == 4) { mean = (const float*)d_in[i]; break; }
    }

    float* out = (float*)d_out;

    const int B = in_sizes[2];                 // 16384
    const int S = in_sizes[0] / (4 * B);       // 256

    bayes_kernel<<<B, 256>>>(A, Bm, BEVa, BEVb, kapa, mean, out, B, S);
}

// round 5
// speedup vs baseline: 8.7994x; 8.7994x over previous
#include <cuda_runtime.h>
#include <cstdint>
#include <math.h>

// bayes_55018531062578
//
// out[b] = sigmoid( BEVb[b]-BEVa[b] + (sum_{s<kapa} B[b,k*,s] - A[b,k*,s]) / kapa[b] )
// k*(b,s) = argmax_k ( log_softmax(mean)_k + gumbel(b,s,k) )
// gumbel noise: JAX partitionable threefry counter mode:
//   bits[i] = o0 ^ o1,  (o0,o1) = threefry2x32(key=(0,42), x=(0, i)),
//   u = bitcast((bits>>9)|0x3f800000) - 1
// Fast argmax:  argmax_k (l_k - log(-log(u+eps)+eps)) == argmax_k w_k / t_k,
//   w_k = softmax(mean)_k,  t_k = -log2(u_k+eps)    (monotone transforms)
// Near-tie fallback replays the reference formula in ACCURATE fp32 (no fp64!).

#define EPSF 1e-20f

__device__ __forceinline__ uint32_t rotl32(uint32_t x, int r) {
    return __funnelshift_l(x, x, r);
}

// threefry2x32, key (0,42), input (0, ctr); returns o0 ^ o1
__device__ __forceinline__ uint32_t threefry_xor(uint32_t ctr) {
    const uint32_t ks0 = 0u;
    const uint32_t ks1 = 42u;
    const uint32_t ks2 = 0x1BD11BDAu ^ 42u;

    uint32_t x0 = ks0;
    uint32_t x1 = ctr + ks1;

#define TF4(a,b,c,d) \
    x0 += x1; x1 = rotl32(x1,(a)); x1 ^= x0; \
    x0 += x1; x1 = rotl32(x1,(b)); x1 ^= x0; \
    x0 += x1; x1 = rotl32(x1,(c)); x1 ^= x0; \
    x0 += x1; x1 = rotl32(x1,(d)); x1 ^= x0;

    TF4(13,15,26,6)   x0 += ks1; x1 += ks2 + 1u;
    TF4(17,29,16,24)  x0 += ks2; x1 += ks0 + 2u;
    TF4(13,15,26,6)   x0 += ks0; x1 += ks1 + 3u;
    TF4(17,29,16,24)  x0 += ks1; x1 += ks2 + 4u;
    TF4(13,15,26,6)   x0 += ks2; x1 += ks0 + 5u;
#undef TF4
    return x0 ^ x1;
}

__device__ __forceinline__ float bits_to_uniform(uint32_t bits) {
    return __uint_as_float((bits >> 9) | 0x3f800000u) - 1.0f;
}

__global__ __launch_bounds__(256, 8)
void bayes_kernel(const float* __restrict__ A,
                  const float* __restrict__ Bm,
                  const float* __restrict__ BEVa,
                  const float* __restrict__ BEVb,
                  const int*   __restrict__ kapa,
                  const float* __restrict__ mean,
                  float* __restrict__ out,
                  int B, int S) {
    const int warp = threadIdx.x >> 5;
    const int lane = threadIdx.x & 31;
    const int b = blockIdx.x * 8 + warp;   // one warp per batch row
    if (b >= B) return;

    // softmax(mean) + accurate fp32 log_softmax (for fallback), per thread.
    const float m0 = mean[0], m1 = mean[1], m2 = mean[2], m3 = mean[3];
    const float mx = fmaxf(fmaxf(m0, m1), fmaxf(m2, m3));
    const float e0 = expf(m0 - mx), e1 = expf(m1 - mx);
    const float e2 = expf(m2 - mx), e3 = expf(m3 - mx);
    const float sum = e0 + e1 + e2 + e3;
    const float inv = 1.0f / sum;
    const float w[4]  = {e0 * inv, e1 * inv, e2 * inv, e3 * inv};
    const float lse   = mx + logf(sum);
    const float lg[4] = {m0 - lse, m1 - lse, m2 - lse, m3 - lse};

    const int kap = kapa[b];
    const float* Ab = A  + (size_t)b * 4 * S;
    const float* Bb = Bm + (size_t)b * 4 * S;

    float diff = 0.0f;   // sum over selected s of (B - A)

    for (int s = lane; s < kap; s += 32) {
        const uint32_t base = ((uint32_t)b * (uint32_t)S + (uint32_t)s) * 4u;

        float u[4], q[4];
#pragma unroll
        for (int k = 0; k < 4; k++) {
            const uint32_t bits = threefry_xor(base + (uint32_t)k);
            u[k] = bits_to_uniform(bits);
            const float t = -__log2f(u[k] + EPSF);   // > 0
            q[k] = __fdividef(w[k], t);
        }

        int   kb = 0;
        float best = q[0], second = -1.0f;
        if (q[1] > best) { second = best; best = q[1]; kb = 1; } else second = q[1];
        if (q[2] > best) { second = best; best = q[2]; kb = 2; } else if (q[2] > second) second = q[2];
        if (q[3] > best) { second = best; best = q[3]; kb = 3; } else if (q[3] > second) second = q[3];

        if (best - second < best * 1e-3f) {
            // accurate fp32 fallback: exact reference formula (no doubles)
            float bs = -INFINITY; int kk = 0;
#pragma unroll
            for (int k = 0; k < 4; k++) {
                const float g  = -logf(-logf(u[k] + EPSF) + EPSF);
                const float sc = lg[k] + g;
                if (sc > bs) { bs = sc; kk = k; }
            }
            kb = kk;
        }

        const size_t off = (size_t)kb * S + s;
        diff += Bb[off] - Ab[off];
    }

    // warp reduction — no shared memory, no barriers
#pragma unroll
    for (int o = 16; o > 0; o >>= 1)
        diff += __shfl_down_sync(0xffffffffu, diff, o);

    if (lane == 0) {
        const float x = BEVb[b] - BEVa[b] + diff / (float)kap;
        out[b] = 1.0f / (1.0f + expf(-x));
    }
}

extern "C" void kernel_launch(void* const* d_in, const int* in_sizes, int n_in,
                              void* d_out, int out_size) {
    // metadata order: outcomeA, outcomeB, BEVa, BEVb, kapa, batch_size, features, mean
    const float* A    = (const float*)d_in[0];
    const float* Bm   = (const float*)d_in[1];
    const float* BEVa = (const float*)d_in[2];
    const float* BEVb = (const float*)d_in[3];
    const int*   kapa = (const int*)  d_in[4];

    // mean is the (only) 4-element input; locate it robustly from the tail
    const float* mean = (const float*)d_in[n_in - 1];
    for (int i = n_in - 1; i >= 5; --i) {
        if (in_sizes[i] == 4) { mean = (const float*)d_in[i]; break; }
    }

    float* out = (float*)d_out;

    const int B = in_sizes[2];                 // 16384
    const int S = in_sizes[0] / (4 * B);       // 256

    bayes_kernel<<<(B + 7) / 8, 256>>>(A, Bm, BEVa, BEVb, kapa, mean, out, B, S);
}

// round 6
// speedup vs baseline: 10.0344x; 1.1404x over previous
#include <cuda_runtime.h>
#include <cstdint>
#include <math.h>

// bayes_55018531062578
//
// out[b] = sigmoid( BEVb[b]-BEVa[b] + (sum_{s<kapa} B[b,k*,s] - A[b,k*,s]) / kapa[b] )
// k*(b,s) = argmax_k ( log_softmax(mean)_k + gumbel(b,s,k) )
// gumbel noise: JAX partitionable threefry counter mode:
//   bits[i] = o0 ^ o1,  (o0,o1) = threefry2x32(key=(0,42), x=(0, i)),
//   u = bitcast((bits>>9)|0x3f800000) - 1
// Fast argmax:  argmax_k (l_k - log(-log(u+eps)+eps)) == argmin_k t_k / w_k,
//   w_k = softmax(mean)_k,  t_k = -log2(u_k+eps)    (monotone transforms)
// Near-tie fallback replays the reference formula in accurate fp32.
//
// Work distribution: one 256-thread block per batch row b; warp c owns
// s in [32c, 32c+32). Every live warp does exactly ONE threefry iteration
// -> uniform block duration (fixes the ceil(kap/32) max-of-8 imbalance that
// capped R5 at occ=61%).

#define EPSF 1e-20f

__device__ __forceinline__ uint32_t rotl32(uint32_t x, int r) {
    return __funnelshift_l(x, x, r);
}

// threefry2x32, key (0,42), input (0, ctr); returns o0 ^ o1
__device__ __forceinline__ uint32_t threefry_xor(uint32_t ctr) {
    const uint32_t ks0 = 0u;
    const uint32_t ks1 = 42u;
    const uint32_t ks2 = 0x1BD11BDAu ^ 42u;

    uint32_t x0 = ks0;
    uint32_t x1 = ctr + ks1;

#define TF4(a,b,c,d) \
    x0 += x1; x1 = rotl32(x1,(a)); x1 ^= x0; \
    x0 += x1; x1 = rotl32(x1,(b)); x1 ^= x0; \
    x0 += x1; x1 = rotl32(x1,(c)); x1 ^= x0; \
    x0 += x1; x1 = rotl32(x1,(d)); x1 ^= x0;

    TF4(13,15,26,6)   x0 += ks1; x1 += ks2 + 1u;
    TF4(17,29,16,24)  x0 += ks2; x1 += ks0 + 2u;
    TF4(13,15,26,6)   x0 += ks0; x1 += ks1 + 3u;
    TF4(17,29,16,24)  x0 += ks1; x1 += ks2 + 4u;
    TF4(13,15,26,6)   x0 += ks2; x1 += ks0 + 5u;
#undef TF4
    return x0 ^ x1;
}

__device__ __forceinline__ float bits_to_uniform(uint32_t bits) {
    return __uint_as_float((bits >> 9) | 0x3f800000u) - 1.0f;
}

__global__ __launch_bounds__(256, 8)
void bayes_kernel(const float* __restrict__ A,
                  const float* __restrict__ Bm,
                  const float* __restrict__ BEVa,
                  const float* __restrict__ BEVb,
                  const int*   __restrict__ kapa,
                  const float* __restrict__ mean,
                  float* __restrict__ out,
                  int S) {
    const int b    = blockIdx.x;
    const int tid  = threadIdx.x;
    const int warp = tid >> 5;
    const int lane = tid & 31;
    const int s    = (warp << 5) + lane;   // == tid; warp c covers [32c,32c+32)

    __shared__ float red[8];

    const int kap = kapa[b];

    // Dead warp: no sample in range. Publish zero partial and exit.
    // (Exited threads do not participate in __syncthreads.)
    if ((warp << 5) >= kap) {
        if (lane == 0) red[warp] = 0.0f;
        return;
    }

    // Prologue: softmax(mean) reciprocals (fast path only needs inv-weights).
    const float m0 = mean[0], m1 = mean[1], m2 = mean[2], m3 = mean[3];
    const float mx = fmaxf(fmaxf(m0, m1), fmaxf(m2, m3));
    const float e0 = __expf(m0 - mx), e1 = __expf(m1 - mx);
    const float e2 = __expf(m2 - mx), e3 = __expf(m3 - mx);
    // argmin t_k * inv_w_k  (sum factor cancels: use 1/e_k directly)
    const float iw[4] = {__fdividef(1.0f, e0), __fdividef(1.0f, e1),
                         __fdividef(1.0f, e2), __fdividef(1.0f, e3)};

    float diff = 0.0f;

    if (s < kap) {
        const uint32_t base = ((uint32_t)b * (uint32_t)S + (uint32_t)s) * 4u;

        float u[4], q[4];
#pragma unroll
        for (int k = 0; k < 4; k++) {
            const uint32_t bits = threefry_xor(base + (uint32_t)k);
            u[k] = bits_to_uniform(bits);
            const float t = -__log2f(u[k] + EPSF);   // > 0
            q[k] = t * iw[k];
        }

        // argmin with runner-up tracking
        int   kb = 0;
        float best = q[0], second = INFINITY;
        if (q[1] < best) { second = best; best = q[1]; kb = 1; } else second = q[1];
        if (q[2] < best) { second = best; best = q[2]; kb = 2; } else if (q[2] < second) second = q[2];
        if (q[3] < best) { second = best; best = q[3]; kb = 3; } else if (q[3] < second) second = q[3];

        if (second - best < best * 1e-3f) {
            // rare accurate fp32 fallback: exact reference formula
            const float se  = e0 + e1 + e2 + e3;
            const float lse = mx + logf(se);
            const float lg[4] = {m0 - lse, m1 - lse, m2 - lse, m3 - lse};
            float bs = -INFINITY; int kk = 0;
#pragma unroll
            for (int k = 0; k < 4; k++) {
                const float g  = -logf(-logf(u[k] + EPSF) + EPSF);
                const float sc = lg[k] + g;
                if (sc > bs) { bs = sc; kk = k; }
            }
            kb = kk;
        }

        const float* Ab = A  + (size_t)b * 4 * S;
        const float* Bb = Bm + (size_t)b * 4 * S;
        const size_t off = (size_t)kb * S + s;
        diff = Bb[off] - Ab[off];
    }

    // warp reduction
#pragma unroll
    for (int o = 16; o > 0; o >>= 1)
        diff += __shfl_down_sync(0xffffffffu, diff, o);
    if (lane == 0) red[warp] = diff;

    __syncthreads();

    if (tid == 0) {
        float tot = 0.0f;
#pragma unroll
        for (int wi = 0; wi < 8; wi++) tot += red[wi];
        const float x = BEVb[b] - BEVa[b] + tot / (float)kap;
        out[b] = 1.0f / (1.0f + expf(-x));
    }
}

extern "C" void kernel_launch(void* const* d_in, const int* in_sizes, int n_in,
                              void* d_out, int out_size) {
    // metadata order: outcomeA, outcomeB, BEVa, BEVb, kapa, batch_size, features, mean
    const float* A    = (const float*)d_in[0];
    const float* Bm   = (const float*)d_in[1];
    const float* BEVa = (const float*)d_in[2];
    const float* BEVb = (const float*)d_in[3];
    const int*   kapa = (const int*)  d_in[4];

    // mean is the (only) 4-element input; locate it robustly from the tail
    const float* mean = (const float*)d_in[n_in - 1];
    for (int i = n_in - 1; i >= 5; --i) {
        if (in_sizes[i] == 4) { mean = (const float*)d_in[i]; break; }
    }

    float* out = (float*)d_out;

    const int B = in_sizes[2];                 // 16384
    const int S = in_sizes[0] / (4 * B);       // 256

    bayes_kernel<<<B, 256>>>(A, Bm, BEVa, BEVb, kapa, mean, out, S);
}